// round 12
// baseline (speedup 1.0000x reference)
#include <cuda_runtime.h>
#include <cuda_bf16.h>
#include <cstdint>

// ---------------------------------------------------------------------------
// 2-layer GRU (H=32, INPUT=4, B=4096, S=512) + FC(32->32) + FC(32->1)
//
// Pass 1: R11 version (2 rows/warp, register weights, cp.async x ring).
// Pass 2: NEW chunked two-phase schedule, 2 rows/warp:
//   per 8-step chunk, Phase A computes x-side gate dots (W_ih1 in a 48-ull
//   register array) into a per-lane smem buffer; Phase B reloads the SAME
//   register array with W_hh1 and runs the recurrence. Register high-water
//   is one weight set (96 regs) -> 3 warps/SMSP instead of 2.
// ---------------------------------------------------------------------------

#define B_ROWS 4096
#define SEQ    512
#define HID    32
#define RING   8
#define CH     8                  // pass-2 chunk length (steps)
#define NC     (SEQ / CH)
#define NWARP  (B_ROWS / 2)       // 2048 warps, 2 rows each

typedef unsigned long long ull;

__device__ float g_h1[(size_t)B_ROWS * SEQ * HID];   // 268 MB scratch

__device__ __forceinline__ ull ffma2(ull a, ull b, ull c) {
    ull d;
    asm("fma.rn.f32x2 %0, %1, %2, %3;" : "=l"(d) : "l"(a), "l"(b), "l"(c));
    return d;
}
__device__ __forceinline__ float hsum2(ull v) {
    float2 r;
    asm("mov.b64 {%0, %1}, %2;" : "=f"(r.x), "=f"(r.y) : "l"(v));
    return r.x + r.y;
}
__device__ __forceinline__ float tanh_ap(float x) {
    float y;
    asm("tanh.approx.f32 %0, %1;" : "=f"(y) : "f"(x));
    return y;
}
__device__ __forceinline__ float sig_ap(float x) {
    return fmaf(0.5f, tanh_ap(0.5f * x), 0.5f);
}
__device__ __forceinline__ void cp_async4(uint32_t smem_addr, const float* gptr) {
    asm volatile("cp.async.ca.shared.global [%0], [%1], 4;"
                 :: "r"(smem_addr), "l"(gptr));
}
__device__ __forceinline__ void cp_async16(uint32_t smem_addr, const float* gptr) {
    asm volatile("cp.async.ca.shared.global [%0], [%1], 16;"
                 :: "r"(smem_addr), "l"(gptr));
}
__device__ __forceinline__ void cp_commit() {
    asm volatile("cp.async.commit_group;");
}
__device__ __forceinline__ void cp_wait_ring() {
    asm volatile("cp.async.wait_group %0;" :: "n"(RING - 1));
}
__device__ __forceinline__ void cp_wait_1() {
    asm volatile("cp.async.wait_group 1;");
}
__device__ __forceinline__ void cp_wait_0() {
    asm volatile("cp.async.wait_group 0;");
}

// ---------------------------------------------------------------------------
// Pass 1: GRU layer 1, 2 rows/warp.  x:[B,S,4] -> h1:[B,S,32]   (R11 version)
// ---------------------------------------------------------------------------
__global__ __launch_bounds__(128, 3)
void gru_layer1_kernel(const float* __restrict__ x,
                       const float* __restrict__ Wih,   // [96,4]
                       const float* __restrict__ Whh,   // [96,32]
                       const float* __restrict__ bih,   // [96]
                       const float* __restrict__ bhh)   // [96]
{
    __shared__ __align__(16) float hbuf[4][2][2][HID];
    __shared__ __align__(16) float xring[4][RING][2][4];

    const int warp = (blockIdx.x * blockDim.x + threadIdx.x) >> 5;
    const int wl   = threadIdx.x >> 5;
    const int lane = threadIdx.x & 31;
    if (warp >= NWARP) return;

    ull whr[16], whz[16], whn[16];
    {
        const ull* pr = reinterpret_cast<const ull*>(Whh + (lane)      * HID);
        const ull* pz = reinterpret_cast<const ull*>(Whh + (32 + lane) * HID);
        const ull* pn = reinterpret_cast<const ull*>(Whh + (64 + lane) * HID);
#pragma unroll
        for (int k = 0; k < 16; k++) { whr[k] = pr[k]; whz[k] = pz[k]; whn[k] = pn[k]; }
    }
    const float4 wir = reinterpret_cast<const float4*>(Wih)[lane];
    const float4 wiz = reinterpret_cast<const float4*>(Wih)[32 + lane];
    const float4 win = reinterpret_cast<const float4*>(Wih)[64 + lane];

    const float br  = bih[lane]      + bhh[lane];
    const float bz  = bih[32 + lane] + bhh[32 + lane];
    const float bin = bih[64 + lane];
    const float bhn = bhh[64 + lane];

    const int r0 = warp * 2, r1 = warp * 2 + 1;
    const float* xs0 = x + (size_t)r0 * SEQ * 4;
    const float* xs1 = x + (size_t)r1 * SEQ * 4;
    float* op0 = g_h1 + (size_t)r0 * SEQ * HID + lane;
    float* op1 = g_h1 + (size_t)r1 * SEQ * HID + lane;

    const uint32_t ring_base =
        (uint32_t)__cvta_generic_to_shared(&xring[wl][0][0][0]);

    const bool ld_act = lane < 8;
    const float* xg = (lane < 4) ? (xs0 + lane) : (xs1 + (lane - 4));

#pragma unroll
    for (int d = 0; d < RING; d++) {
        if (ld_act) cp_async4(ring_base + d * 32 + lane * 4, xg + d * 4);
        cp_commit();
    }

    float h0 = 0.0f, h1 = 0.0f;
#pragma unroll 1
    for (int s = 0; s < SEQ; s++) {
        hbuf[wl][s & 1][0][lane] = h0;
        hbuf[wl][s & 1][1][lane] = h1;
        cp_wait_ring();
        __syncwarp();

        const float4 xv0 =
            *reinterpret_cast<const float4*>(&xring[wl][s & (RING - 1)][0][0]);
        const float4 xv1 =
            *reinterpret_cast<const float4*>(&xring[wl][s & (RING - 1)][1][0]);
        const ulonglong2* hp0 =
            reinterpret_cast<const ulonglong2*>(&hbuf[wl][s & 1][0][0]);
        const ulonglong2* hp1 =
            reinterpret_cast<const ulonglong2*>(&hbuf[wl][s & 1][1][0]);

        if (ld_act && s + RING < SEQ)
            cp_async4(ring_base + ((s + RING) & (RING - 1)) * 32 + lane * 4,
                      xg + (s + RING) * 4);
        cp_commit();

        float ar0 = br, az0 = bz, xn0 = bin;
        float ar1 = br, az1 = bz, xn1 = bin;
        ar0 = fmaf(wir.x, xv0.x, ar0); ar0 = fmaf(wir.y, xv0.y, ar0);
        ar0 = fmaf(wir.z, xv0.z, ar0); ar0 = fmaf(wir.w, xv0.w, ar0);
        az0 = fmaf(wiz.x, xv0.x, az0); az0 = fmaf(wiz.y, xv0.y, az0);
        az0 = fmaf(wiz.z, xv0.z, az0); az0 = fmaf(wiz.w, xv0.w, az0);
        xn0 = fmaf(win.x, xv0.x, xn0); xn0 = fmaf(win.y, xv0.y, xn0);
        xn0 = fmaf(win.z, xv0.z, xn0); xn0 = fmaf(win.w, xv0.w, xn0);
        ar1 = fmaf(wir.x, xv1.x, ar1); ar1 = fmaf(wir.y, xv1.y, ar1);
        ar1 = fmaf(wir.z, xv1.z, ar1); ar1 = fmaf(wir.w, xv1.w, ar1);
        az1 = fmaf(wiz.x, xv1.x, az1); az1 = fmaf(wiz.y, xv1.y, az1);
        az1 = fmaf(wiz.z, xv1.z, az1); az1 = fmaf(wiz.w, xv1.w, az1);
        xn1 = fmaf(win.x, xv1.x, xn1); xn1 = fmaf(win.y, xv1.y, xn1);
        xn1 = fmaf(win.z, xv1.z, xn1); xn1 = fmaf(win.w, xv1.w, xn1);

        ull ra0 = 0ull, za0 = 0ull, na0 = 0ull;
        ull ra1 = 0ull, za1 = 0ull, na1 = 0ull;
#pragma unroll
        for (int k = 0; k < 8; k++) {
            const ulonglong2 hv0 = hp0[k];
            const ulonglong2 hv1 = hp1[k];
            ra0 = ffma2(whr[2 * k],     hv0.x, ra0);
            za0 = ffma2(whz[2 * k],     hv0.x, za0);
            na0 = ffma2(whn[2 * k],     hv0.x, na0);
            ra1 = ffma2(whr[2 * k],     hv1.x, ra1);
            za1 = ffma2(whz[2 * k],     hv1.x, za1);
            na1 = ffma2(whn[2 * k],     hv1.x, na1);
            ra0 = ffma2(whr[2 * k + 1], hv0.y, ra0);
            za0 = ffma2(whz[2 * k + 1], hv0.y, za0);
            na0 = ffma2(whn[2 * k + 1], hv0.y, na0);
            ra1 = ffma2(whr[2 * k + 1], hv1.y, ra1);
            za1 = ffma2(whz[2 * k + 1], hv1.y, za1);
            na1 = ffma2(whn[2 * k + 1], hv1.y, na1);
        }
        ar0 += hsum2(ra0);  az0 += hsum2(za0);
        ar1 += hsum2(ra1);  az1 += hsum2(za1);
        const float hn0 = bhn + hsum2(na0);
        const float hn1 = bhn + hsum2(na1);

        const float rr0 = sig_ap(ar0);
        const float zz0 = sig_ap(az0);
        const float nn0 = tanh_ap(fmaf(rr0, hn0, xn0));
        h0 = fmaf(zz0, h0 - nn0, nn0);
        const float rr1 = sig_ap(ar1);
        const float zz1 = sig_ap(az1);
        const float nn1 = tanh_ap(fmaf(rr1, hn1, xn1));
        h1 = fmaf(zz1, h1 - nn1, nn1);

        op0[(size_t)s * HID] = h0;
        op1[(size_t)s * HID] = h1;
    }
}

// ---------------------------------------------------------------------------
// Pass 2: chunked two-phase GRU layer 2 + FC, 2 rows/warp.
// ---------------------------------------------------------------------------
__global__ __launch_bounds__(128, 3)
void gru_layer2_fc_kernel(const float* __restrict__ Wih,   // [96,32]
                          const float* __restrict__ Whh,   // [96,32]
                          const float* __restrict__ bih,   // [96]
                          const float* __restrict__ bhh,   // [96]
                          const float* __restrict__ Wfc2,  // [32,32]
                          const float* __restrict__ bfc2,  // [32]
                          const float* __restrict__ Wfc,   // [1,32]
                          const float* __restrict__ bfc,   // [1]
                          float* __restrict__ out)
{
    __shared__ __align__(16) float hbuf[4][2][2][HID];        // 2 KB
    __shared__ __align__(16) float h1c [4][2][CH][2][HID];    // 16 KB
    __shared__ __align__(16) float xgb [4][CH][2][3][HID];    // 24 KB

    const int warp = (blockIdx.x * blockDim.x + threadIdx.x) >> 5;
    const int wl   = threadIdx.x >> 5;
    const int lane = threadIdx.x & 31;
    if (warp >= NWARP) return;

    const float br  = bih[lane]      + bhh[lane];
    const float bz  = bih[32 + lane] + bhh[32 + lane];
    const float bin = bih[64 + lane];
    const float bhn = bhh[64 + lane];

    const float* xs0 = g_h1 + (size_t)(warp * 2)     * SEQ * HID;
    const float* xs1 = g_h1 + (size_t)(warp * 2 + 1) * SEQ * HID;

    const uint32_t h1c_base =
        (uint32_t)__cvta_generic_to_shared(&h1c[wl][0][0][0][0]);

    // Chunk loader: 2 rows x CH steps x 128B = 2 KB -> 4 x cp.async.16 / lane.
    auto load_chunk = [&](int c, int buf) {
#pragma unroll
        for (int i = 0; i < 4; i++) {
            const int idx = i * 32 + lane;        // 0..127
            const int row = idx >> 6;             // 0..1
            const int rem = idx & 63;
            const int t   = rem >> 3;             // 0..7
            const int q   = rem & 7;              // 0..7 (16B quarter)
            const float* src = (row ? xs1 : xs0) + (size_t)(c * CH + t) * HID + q * 4;
            const uint32_t dst = h1c_base + buf * (CH * 2 * HID * 4)
                               + t * (2 * HID * 4) + row * (HID * 4) + q * 16;
            cp_async16(dst, src);
        }
        cp_commit();
    };

    load_chunk(0, 0);

    // Phase-shared register weight array (48 ull = 96 regs high-water).
    ull W[48];

    float h0 = 0.0f, h1 = 0.0f;
#pragma unroll 1
    for (int c = 0; c < NC; c++) {
        if (c + 1 < NC) { load_chunk(c + 1, (c + 1) & 1); cp_wait_1(); }
        else           { cp_wait_0(); }
        __syncwarp();

        // ---------------- Phase A: x-side dots for the chunk ----------------
        {
            const ull* p0 = reinterpret_cast<const ull*>(Wih + (lane)      * HID);
            const ull* p1 = reinterpret_cast<const ull*>(Wih + (32 + lane) * HID);
            const ull* p2 = reinterpret_cast<const ull*>(Wih + (64 + lane) * HID);
#pragma unroll
            for (int k = 0; k < 16; k++) {
                W[k] = p0[k]; W[16 + k] = p1[k]; W[32 + k] = p2[k];
            }
        }
#pragma unroll 2
        for (int t = 0; t < CH; t++) {
            const ulonglong2* x0 =
                reinterpret_cast<const ulonglong2*>(&h1c[wl][c & 1][t][0][0]);
            const ulonglong2* x1 =
                reinterpret_cast<const ulonglong2*>(&h1c[wl][c & 1][t][1][0]);
            ull r0 = 0ull, z0 = 0ull, n0 = 0ull;
            ull r1 = 0ull, z1 = 0ull, n1 = 0ull;
#pragma unroll
            for (int k = 0; k < 8; k++) {
                const ulonglong2 v0 = x0[k];
                const ulonglong2 v1 = x1[k];
                r0 = ffma2(W[2 * k],          v0.x, r0);
                z0 = ffma2(W[16 + 2 * k],     v0.x, z0);
                n0 = ffma2(W[32 + 2 * k],     v0.x, n0);
                r1 = ffma2(W[2 * k],          v1.x, r1);
                z1 = ffma2(W[16 + 2 * k],     v1.x, z1);
                n1 = ffma2(W[32 + 2 * k],     v1.x, n1);
                r0 = ffma2(W[2 * k + 1],      v0.y, r0);
                z0 = ffma2(W[16 + 2 * k + 1], v0.y, z0);
                n0 = ffma2(W[32 + 2 * k + 1], v0.y, n0);
                r1 = ffma2(W[2 * k + 1],      v1.y, r1);
                z1 = ffma2(W[16 + 2 * k + 1], v1.y, z1);
                n1 = ffma2(W[32 + 2 * k + 1], v1.y, n1);
            }
            // lane writes/reads only its own slots -> no sync needed
            xgb[wl][t][0][0][lane] = br  + hsum2(r0);
            xgb[wl][t][0][1][lane] = bz  + hsum2(z0);
            xgb[wl][t][0][2][lane] = bin + hsum2(n0);
            xgb[wl][t][1][0][lane] = br  + hsum2(r1);
            xgb[wl][t][1][1][lane] = bz  + hsum2(z1);
            xgb[wl][t][1][2][lane] = bin + hsum2(n1);
        }

        // ---------------- Phase B: recurrence over the chunk ----------------
        {
            const ull* p3 = reinterpret_cast<const ull*>(Whh + (lane)      * HID);
            const ull* p4 = reinterpret_cast<const ull*>(Whh + (32 + lane) * HID);
            const ull* p5 = reinterpret_cast<const ull*>(Whh + (64 + lane) * HID);
#pragma unroll
            for (int k = 0; k < 16; k++) {
                W[k] = p3[k]; W[16 + k] = p4[k]; W[32 + k] = p5[k];
            }
        }
#pragma unroll 2
        for (int t = 0; t < CH; t++) {
            hbuf[wl][t & 1][0][lane] = h0;
            hbuf[wl][t & 1][1][lane] = h1;
            __syncwarp();
            const ulonglong2* hp0 =
                reinterpret_cast<const ulonglong2*>(&hbuf[wl][t & 1][0][0]);
            const ulonglong2* hp1 =
                reinterpret_cast<const ulonglong2*>(&hbuf[wl][t & 1][1][0]);

            ull r0 = 0ull, z0 = 0ull, n0 = 0ull;
            ull r1 = 0ull, z1 = 0ull, n1 = 0ull;
#pragma unroll
            for (int k = 0; k < 8; k++) {
                const ulonglong2 v0 = hp0[k];
                const ulonglong2 v1 = hp1[k];
                r0 = ffma2(W[2 * k],          v0.x, r0);
                z0 = ffma2(W[16 + 2 * k],     v0.x, z0);
                n0 = ffma2(W[32 + 2 * k],     v0.x, n0);
                r1 = ffma2(W[2 * k],          v1.x, r1);
                z1 = ffma2(W[16 + 2 * k],     v1.x, z1);
                n1 = ffma2(W[32 + 2 * k],     v1.x, n1);
                r0 = ffma2(W[2 * k + 1],      v0.y, r0);
                z0 = ffma2(W[16 + 2 * k + 1], v0.y, z0);
                n0 = ffma2(W[32 + 2 * k + 1], v0.y, n0);
                r1 = ffma2(W[2 * k + 1],      v1.y, r1);
                z1 = ffma2(W[16 + 2 * k + 1], v1.y, z1);
                n1 = ffma2(W[32 + 2 * k + 1], v1.y, n1);
            }
            const float ar0 = xgb[wl][t][0][0][lane] + hsum2(r0);
            const float az0 = xgb[wl][t][0][1][lane] + hsum2(z0);
            const float xn0 = xgb[wl][t][0][2][lane];
            const float hn0 = bhn + hsum2(n0);
            const float ar1 = xgb[wl][t][1][0][lane] + hsum2(r1);
            const float az1 = xgb[wl][t][1][1][lane] + hsum2(z1);
            const float xn1 = xgb[wl][t][1][2][lane];
            const float hn1 = bhn + hsum2(n1);

            const float rr0 = sig_ap(ar0);
            const float zz0 = sig_ap(az0);
            const float nn0 = tanh_ap(fmaf(rr0, hn0, xn0));
            h0 = fmaf(zz0, h0 - nn0, nn0);
            const float rr1 = sig_ap(ar1);
            const float zz1 = sig_ap(az1);
            const float nn1 = tanh_ap(fmaf(rr1, hn1, xn1));
            h1 = fmaf(zz1, h1 - nn1, nn1);
        }
    }

    // FC2 + FC epilogue for both rows
    {
        hbuf[wl][0][0][lane] = h0;
        hbuf[wl][0][1][lane] = h1;
        __syncwarp();
        const ulonglong2* hp0 =
            reinterpret_cast<const ulonglong2*>(&hbuf[wl][0][0][0]);
        const ulonglong2* hp1 =
            reinterpret_cast<const ulonglong2*>(&hbuf[wl][0][1][0]);
        const ull* wf = reinterpret_cast<const ull*>(Wfc2 + lane * HID);
        ull a0 = 0ull, a1 = 0ull;
#pragma unroll
        for (int k = 0; k < 8; k++) {
            const ulonglong2 hv0 = hp0[k];
            const ulonglong2 hv1 = hp1[k];
            a0 = ffma2(wf[2 * k],     hv0.x, a0);
            a1 = ffma2(wf[2 * k],     hv1.x, a1);
            a0 = ffma2(wf[2 * k + 1], hv0.y, a0);
            a1 = ffma2(wf[2 * k + 1], hv1.y, a1);
        }
        const float bf2 = __ldg(bfc2 + lane);
        const float o0 = bf2 + hsum2(a0);
        const float o1 = bf2 + hsum2(a1);

        const float wfc = __ldg(Wfc + lane);
        float p0 = wfc * o0;
        float p1 = wfc * o1;
#pragma unroll
        for (int off = 16; off > 0; off >>= 1) {
            p0 += __shfl_xor_sync(0xffffffffu, p0, off);
            p1 += __shfl_xor_sync(0xffffffffu, p1, off);
        }
        if (lane == 0) {
            const float bb = __ldg(bfc);
            out[warp * 2]     = p0 + bb;
            out[warp * 2 + 1] = p1 + bb;
        }
    }
}

// ---------------------------------------------------------------------------
// Launch
// ---------------------------------------------------------------------------
extern "C" void kernel_launch(void* const* d_in, const int* in_sizes, int n_in,
                              void* d_out, int out_size)
{
    const float* x     = (const float*)d_in[0];
    const float* Wih0  = (const float*)d_in[1];
    const float* Whh0  = (const float*)d_in[2];
    const float* bih0  = (const float*)d_in[3];
    const float* bhh0  = (const float*)d_in[4];
    const float* Wih1  = (const float*)d_in[5];
    const float* Whh1  = (const float*)d_in[6];
    const float* bih1  = (const float*)d_in[7];
    const float* bhh1  = (const float*)d_in[8];
    const float* Wfc2  = (const float*)d_in[9];
    const float* bfc2  = (const float*)d_in[10];
    const float* Wfc   = (const float*)d_in[11];
    const float* bfc   = (const float*)d_in[12];
    float* out = (float*)d_out;

    const int threads = 128;                 // 4 warps = 8 rows per CTA
    const int blocks  = NWARP / 4;           // 512 CTAs

    gru_layer1_kernel<<<blocks, threads>>>(x, Wih0, Whh0, bih0, bhh0);
    gru_layer2_fc_kernel<<<blocks, threads>>>(Wih1, Whh1, bih1, bhh1,
                                              Wfc2, bfc2, Wfc, bfc, out);
}

// round 13
// speedup vs baseline: 2.5113x; 2.5113x over previous
#include <cuda_runtime.h>
#include <cuda_bf16.h>
#include <cstdint>

// ---------------------------------------------------------------------------
// 2-layer GRU (H=32, INPUT=4, B=4096, S=512) + FC(32->32) + FC(32->1)
//
// Pass 1 (fused): layer-1 recurrence AND layer-2's x-side GEMM. At step s,
//   hbuf holds h1[s-1] for the recurrence; the same broadcast operands feed
//   xg2[s-1] = W_ih1 . h1[s-1] accumulated in the same k-loop. Writes
//   xg[B,S,96] (biases folded), not h1.
// Pass 2 (slim): pure h-side recurrence (96 weight regs -> 3 warps/SMSP)
//   + FC epilogue. x-gates arrive precomputed via cp.async ring.
// ---------------------------------------------------------------------------

#define B_ROWS 4096
#define SEQ    512
#define HID    32
#define RING   8
#define NWARP  (B_ROWS / 2)       // 2048 warps, 2 rows each

typedef unsigned long long ull;

__device__ float g_xg[(size_t)B_ROWS * SEQ * 96];    // 805 MB scratch

__device__ __forceinline__ ull ffma2(ull a, ull b, ull c) {
    ull d;
    asm("fma.rn.f32x2 %0, %1, %2, %3;" : "=l"(d) : "l"(a), "l"(b), "l"(c));
    return d;
}
__device__ __forceinline__ float hsum2(ull v) {
    float2 r;
    asm("mov.b64 {%0, %1}, %2;" : "=f"(r.x), "=f"(r.y) : "l"(v));
    return r.x + r.y;
}
__device__ __forceinline__ float tanh_ap(float x) {
    float y;
    asm("tanh.approx.f32 %0, %1;" : "=f"(y) : "f"(x));
    return y;
}
__device__ __forceinline__ float sig_ap(float x) {
    return fmaf(0.5f, tanh_ap(0.5f * x), 0.5f);
}
__device__ __forceinline__ void cp_async4(uint32_t smem_addr, const float* gptr) {
    asm volatile("cp.async.ca.shared.global [%0], [%1], 4;"
                 :: "r"(smem_addr), "l"(gptr));
}
__device__ __forceinline__ void cp_commit() {
    asm volatile("cp.async.commit_group;");
}
__device__ __forceinline__ void cp_wait_ring() {
    asm volatile("cp.async.wait_group %0;" :: "n"(RING - 1));
}

// ---------------------------------------------------------------------------
// Pass 1: GRU layer 1 + layer-2 x-side GEMM, 2 rows/warp.
//   x:[B,S,4] -> xg:[B,S,96]  (xg[s] = W_ih1 . h1[s] + folded biases)
// ---------------------------------------------------------------------------
__global__ __launch_bounds__(128, 2)
void gru_layer1_fused_kernel(const float* __restrict__ x,
                             const float* __restrict__ Wih0,  // [96,4]
                             const float* __restrict__ Whh0,  // [96,32]
                             const float* __restrict__ bih0,  // [96]
                             const float* __restrict__ bhh0,  // [96]
                             const float* __restrict__ Wih1,  // [96,32]
                             const float* __restrict__ bih1,  // [96]
                             const float* __restrict__ bhh1)  // [96]
{
    __shared__ __align__(16) float hbuf[4][2][2][HID];
    __shared__ __align__(16) float xring[4][RING][2][4];

    const int warp = (blockIdx.x * blockDim.x + threadIdx.x) >> 5;
    const int wl   = threadIdx.x >> 5;
    const int lane = threadIdx.x & 31;
    if (warp >= NWARP) return;

    // Layer-1 recurrent weights (96 regs)
    ull whr[16], whz[16], whn[16];
    {
        const ull* pr = reinterpret_cast<const ull*>(Whh0 + (lane)      * HID);
        const ull* pz = reinterpret_cast<const ull*>(Whh0 + (32 + lane) * HID);
        const ull* pn = reinterpret_cast<const ull*>(Whh0 + (64 + lane) * HID);
#pragma unroll
        for (int k = 0; k < 16; k++) { whr[k] = pr[k]; whz[k] = pz[k]; whn[k] = pn[k]; }
    }
    // Layer-2 x-side weights (96 regs)
    ull wxr[16], wxz[16], wxn[16];
    {
        const ull* p0 = reinterpret_cast<const ull*>(Wih1 + (lane)      * HID);
        const ull* p1 = reinterpret_cast<const ull*>(Wih1 + (32 + lane) * HID);
        const ull* p2 = reinterpret_cast<const ull*>(Wih1 + (64 + lane) * HID);
#pragma unroll
        for (int k = 0; k < 16; k++) { wxr[k] = p0[k]; wxz[k] = p1[k]; wxn[k] = p2[k]; }
    }
    const float4 wir = reinterpret_cast<const float4*>(Wih0)[lane];
    const float4 wiz = reinterpret_cast<const float4*>(Wih0)[32 + lane];
    const float4 win = reinterpret_cast<const float4*>(Wih0)[64 + lane];

    const float br  = bih0[lane]      + bhh0[lane];
    const float bz  = bih0[32 + lane] + bhh0[32 + lane];
    const float bin = bih0[64 + lane];
    const float bhn = bhh0[64 + lane];
    // xg biases: r,z gates fold both layer-2 biases; n-gate folds bih1 only.
    const float gxr = bih1[lane]      + bhh1[lane];
    const float gxz = bih1[32 + lane] + bhh1[32 + lane];
    const float gxn = bih1[64 + lane];

    const int r0 = warp * 2, r1 = warp * 2 + 1;
    const float* xs0 = x + (size_t)r0 * SEQ * 4;
    const float* xs1 = x + (size_t)r1 * SEQ * 4;
    float* go0 = g_xg + (size_t)r0 * SEQ * 96;
    float* go1 = g_xg + (size_t)r1 * SEQ * 96;

    const uint32_t ring_base =
        (uint32_t)__cvta_generic_to_shared(&xring[wl][0][0][0]);

    const bool ld_act = lane < 8;
    const float* xg = (lane < 4) ? (xs0 + lane) : (xs1 + (lane - 4));

#pragma unroll
    for (int d = 0; d < RING; d++) {
        if (ld_act) cp_async4(ring_base + d * 32 + lane * 4, xg + d * 4);
        cp_commit();
    }

    float h0 = 0.0f, h1 = 0.0f;
#pragma unroll 1
    for (int s = 0; s < SEQ; s++) {
        hbuf[wl][s & 1][0][lane] = h0;   // = h1-layer state after step s-1
        hbuf[wl][s & 1][1][lane] = h1;
        cp_wait_ring();
        __syncwarp();

        const float4 xv0 =
            *reinterpret_cast<const float4*>(&xring[wl][s & (RING - 1)][0][0]);
        const float4 xv1 =
            *reinterpret_cast<const float4*>(&xring[wl][s & (RING - 1)][1][0]);
        const ulonglong2* hp0 =
            reinterpret_cast<const ulonglong2*>(&hbuf[wl][s & 1][0][0]);
        const ulonglong2* hp1 =
            reinterpret_cast<const ulonglong2*>(&hbuf[wl][s & 1][1][0]);

        if (ld_act && s + RING < SEQ)
            cp_async4(ring_base + ((s + RING) & (RING - 1)) * 32 + lane * 4,
                      xg + (s + RING) * 4);
        cp_commit();

        float ar0 = br, az0 = bz, xn0 = bin;
        float ar1 = br, az1 = bz, xn1 = bin;
        ar0 = fmaf(wir.x, xv0.x, ar0); ar0 = fmaf(wir.y, xv0.y, ar0);
        ar0 = fmaf(wir.z, xv0.z, ar0); ar0 = fmaf(wir.w, xv0.w, ar0);
        az0 = fmaf(wiz.x, xv0.x, az0); az0 = fmaf(wiz.y, xv0.y, az0);
        az0 = fmaf(wiz.z, xv0.z, az0); az0 = fmaf(wiz.w, xv0.w, az0);
        xn0 = fmaf(win.x, xv0.x, xn0); xn0 = fmaf(win.y, xv0.y, xn0);
        xn0 = fmaf(win.z, xv0.z, xn0); xn0 = fmaf(win.w, xv0.w, xn0);
        ar1 = fmaf(wir.x, xv1.x, ar1); ar1 = fmaf(wir.y, xv1.y, ar1);
        ar1 = fmaf(wir.z, xv1.z, ar1); ar1 = fmaf(wir.w, xv1.w, ar1);
        az1 = fmaf(wiz.x, xv1.x, az1); az1 = fmaf(wiz.y, xv1.y, az1);
        az1 = fmaf(wiz.z, xv1.z, az1); az1 = fmaf(wiz.w, xv1.w, az1);
        xn1 = fmaf(win.x, xv1.x, xn1); xn1 = fmaf(win.y, xv1.y, xn1);
        xn1 = fmaf(win.z, xv1.z, xn1); xn1 = fmaf(win.w, xv1.w, xn1);

        // Combined k-loop: layer-1 recurrence + xg GEMM share the hv loads.
        ull ra0 = 0ull, za0 = 0ull, na0 = 0ull;
        ull ra1 = 0ull, za1 = 0ull, na1 = 0ull;
        ull qr0 = 0ull, qz0 = 0ull, qn0 = 0ull;
        ull qr1 = 0ull, qz1 = 0ull, qn1 = 0ull;
#pragma unroll
        for (int k = 0; k < 8; k++) {
            const ulonglong2 hv0 = hp0[k];
            const ulonglong2 hv1 = hp1[k];
            ra0 = ffma2(whr[2 * k],     hv0.x, ra0);
            za0 = ffma2(whz[2 * k],     hv0.x, za0);
            na0 = ffma2(whn[2 * k],     hv0.x, na0);
            qr0 = ffma2(wxr[2 * k],     hv0.x, qr0);
            qz0 = ffma2(wxz[2 * k],     hv0.x, qz0);
            qn0 = ffma2(wxn[2 * k],     hv0.x, qn0);
            ra1 = ffma2(whr[2 * k],     hv1.x, ra1);
            za1 = ffma2(whz[2 * k],     hv1.x, za1);
            na1 = ffma2(whn[2 * k],     hv1.x, na1);
            qr1 = ffma2(wxr[2 * k],     hv1.x, qr1);
            qz1 = ffma2(wxz[2 * k],     hv1.x, qz1);
            qn1 = ffma2(wxn[2 * k],     hv1.x, qn1);
            ra0 = ffma2(whr[2 * k + 1], hv0.y, ra0);
            za0 = ffma2(whz[2 * k + 1], hv0.y, za0);
            na0 = ffma2(whn[2 * k + 1], hv0.y, na0);
            qr0 = ffma2(wxr[2 * k + 1], hv0.y, qr0);
            qz0 = ffma2(wxz[2 * k + 1], hv0.y, qz0);
            qn0 = ffma2(wxn[2 * k + 1], hv0.y, qn0);
            ra1 = ffma2(whr[2 * k + 1], hv1.y, ra1);
            za1 = ffma2(whz[2 * k + 1], hv1.y, za1);
            na1 = ffma2(whn[2 * k + 1], hv1.y, na1);
            qr1 = ffma2(wxr[2 * k + 1], hv1.y, qr1);
            qz1 = ffma2(wxz[2 * k + 1], hv1.y, qz1);
            qn1 = ffma2(wxn[2 * k + 1], hv1.y, qn1);
        }

        // Store xg for step s-1 (hbuf held h1[s-1]).
        if (s) {
            float* o0 = go0 + (size_t)(s - 1) * 96;
            float* o1 = go1 + (size_t)(s - 1) * 96;
            o0[lane]      = gxr + hsum2(qr0);
            o0[32 + lane] = gxz + hsum2(qz0);
            o0[64 + lane] = gxn + hsum2(qn0);
            o1[lane]      = gxr + hsum2(qr1);
            o1[32 + lane] = gxz + hsum2(qz1);
            o1[64 + lane] = gxn + hsum2(qn1);
        }

        ar0 += hsum2(ra0);  az0 += hsum2(za0);
        ar1 += hsum2(ra1);  az1 += hsum2(za1);
        const float hn0 = bhn + hsum2(na0);
        const float hn1 = bhn + hsum2(na1);

        const float rr0 = sig_ap(ar0);
        const float zz0 = sig_ap(az0);
        const float nn0 = tanh_ap(fmaf(rr0, hn0, xn0));
        h0 = fmaf(zz0, h0 - nn0, nn0);
        const float rr1 = sig_ap(ar1);
        const float zz1 = sig_ap(az1);
        const float nn1 = tanh_ap(fmaf(rr1, hn1, xn1));
        h1 = fmaf(zz1, h1 - nn1, nn1);
    }

    // Epilogue: xg for the final step (h1[SEQ-1]).
    {
        hbuf[wl][0][0][lane] = h0;
        hbuf[wl][0][1][lane] = h1;
        __syncwarp();
        const ulonglong2* hp0 =
            reinterpret_cast<const ulonglong2*>(&hbuf[wl][0][0][0]);
        const ulonglong2* hp1 =
            reinterpret_cast<const ulonglong2*>(&hbuf[wl][0][1][0]);
        ull qr0 = 0ull, qz0 = 0ull, qn0 = 0ull;
        ull qr1 = 0ull, qz1 = 0ull, qn1 = 0ull;
#pragma unroll
        for (int k = 0; k < 8; k++) {
            const ulonglong2 hv0 = hp0[k];
            const ulonglong2 hv1 = hp1[k];
            qr0 = ffma2(wxr[2 * k],     hv0.x, qr0);
            qz0 = ffma2(wxz[2 * k],     hv0.x, qz0);
            qn0 = ffma2(wxn[2 * k],     hv0.x, qn0);
            qr1 = ffma2(wxr[2 * k],     hv1.x, qr1);
            qz1 = ffma2(wxz[2 * k],     hv1.x, qz1);
            qn1 = ffma2(wxn[2 * k],     hv1.x, qn1);
            qr0 = ffma2(wxr[2 * k + 1], hv0.y, qr0);
            qz0 = ffma2(wxz[2 * k + 1], hv0.y, qz0);
            qn0 = ffma2(wxn[2 * k + 1], hv0.y, qn0);
            qr1 = ffma2(wxr[2 * k + 1], hv1.y, qr1);
            qz1 = ffma2(wxz[2 * k + 1], hv1.y, qz1);
            qn1 = ffma2(wxn[2 * k + 1], hv1.y, qn1);
        }
        float* o0 = go0 + (size_t)(SEQ - 1) * 96;
        float* o1 = go1 + (size_t)(SEQ - 1) * 96;
        o0[lane]      = gxr + hsum2(qr0);
        o0[32 + lane] = gxz + hsum2(qz0);
        o0[64 + lane] = gxn + hsum2(qn0);
        o1[lane]      = gxr + hsum2(qr1);
        o1[32 + lane] = gxz + hsum2(qz1);
        o1[64 + lane] = gxn + hsum2(qn1);
    }
}

// ---------------------------------------------------------------------------
// Pass 2: slim layer-2 recurrence + FC, 2 rows/warp.  xg:[B,S,96] -> out:[B]
// ---------------------------------------------------------------------------
__global__ __launch_bounds__(128, 3)
void gru_layer2_fc_kernel(const float* __restrict__ Whh,   // [96,32]
                          const float* __restrict__ bhh,   // [96]
                          const float* __restrict__ Wfc2,  // [32,32]
                          const float* __restrict__ bfc2,  // [32]
                          const float* __restrict__ Wfc,   // [1,32]
                          const float* __restrict__ bfc,   // [1]
                          float* __restrict__ out)
{
    __shared__ __align__(16) float hbuf[4][2][2][HID];      // 2 KB
    __shared__ __align__(16) float xring[4][RING][2][96];   // 24 KB

    const int warp = (blockIdx.x * blockDim.x + threadIdx.x) >> 5;
    const int wl   = threadIdx.x >> 5;
    const int lane = threadIdx.x & 31;
    if (warp >= NWARP) return;

    ull whr[16], whz[16], whn[16];
    {
        const ull* p3 = reinterpret_cast<const ull*>(Whh + (lane)      * HID);
        const ull* p4 = reinterpret_cast<const ull*>(Whh + (32 + lane) * HID);
        const ull* p5 = reinterpret_cast<const ull*>(Whh + (64 + lane) * HID);
#pragma unroll
        for (int k = 0; k < 16; k++) { whr[k] = p3[k]; whz[k] = p4[k]; whn[k] = p5[k]; }
    }
    const float bhn = bhh[64 + lane];

    const float* xs0 = g_xg + (size_t)(warp * 2)     * SEQ * 96;
    const float* xs1 = g_xg + (size_t)(warp * 2 + 1) * SEQ * 96;

    const uint32_t ring_base =
        (uint32_t)__cvta_generic_to_shared(&xring[wl][0][0][0]);

    // 768B per ring slot: 2 rows x 96 floats; 6 cp.async4 per lane.
#pragma unroll
    for (int d = 0; d < RING; d++) {
        const uint32_t rb = ring_base + d * 768;
        cp_async4(rb + lane * 4,       xs0 + d * 96 + lane);
        cp_async4(rb + 128 + lane * 4, xs0 + d * 96 + 32 + lane);
        cp_async4(rb + 256 + lane * 4, xs0 + d * 96 + 64 + lane);
        cp_async4(rb + 384 + lane * 4, xs1 + d * 96 + lane);
        cp_async4(rb + 512 + lane * 4, xs1 + d * 96 + 32 + lane);
        cp_async4(rb + 640 + lane * 4, xs1 + d * 96 + 64 + lane);
        cp_commit();
    }

    float h0 = 0.0f, h1 = 0.0f;
#pragma unroll 1
    for (int s = 0; s < SEQ; s++) {
        hbuf[wl][s & 1][0][lane] = h0;
        hbuf[wl][s & 1][1][lane] = h1;
        cp_wait_ring();
        __syncwarp();

        const float* xrow = &xring[wl][s & (RING - 1)][0][0];
        const float xr0 = xrow[lane];
        const float xz0 = xrow[32 + lane];
        const float xn0 = xrow[64 + lane];
        const float xr1 = xrow[96 + lane];
        const float xz1 = xrow[128 + lane];
        const float xn1 = xrow[160 + lane];
        const ulonglong2* hp0 =
            reinterpret_cast<const ulonglong2*>(&hbuf[wl][s & 1][0][0]);
        const ulonglong2* hp1 =
            reinterpret_cast<const ulonglong2*>(&hbuf[wl][s & 1][1][0]);

        if (s + RING < SEQ) {
            const uint32_t rb = ring_base + ((s + RING) & (RING - 1)) * 768;
            const float* g0 = xs0 + (s + RING) * 96;
            const float* g1 = xs1 + (s + RING) * 96;
            cp_async4(rb + lane * 4,       g0 + lane);
            cp_async4(rb + 128 + lane * 4, g0 + 32 + lane);
            cp_async4(rb + 256 + lane * 4, g0 + 64 + lane);
            cp_async4(rb + 384 + lane * 4, g1 + lane);
            cp_async4(rb + 512 + lane * 4, g1 + 32 + lane);
            cp_async4(rb + 640 + lane * 4, g1 + 64 + lane);
        }
        cp_commit();

        ull r0 = 0ull, z0 = 0ull, n0 = 0ull;
        ull r1 = 0ull, z1 = 0ull, n1 = 0ull;
#pragma unroll
        for (int k = 0; k < 8; k++) {
            const ulonglong2 hv0 = hp0[k];
            const ulonglong2 hv1 = hp1[k];
            r0 = ffma2(whr[2 * k],     hv0.x, r0);
            z0 = ffma2(whz[2 * k],     hv0.x, z0);
            n0 = ffma2(whn[2 * k],     hv0.x, n0);
            r1 = ffma2(whr[2 * k],     hv1.x, r1);
            z1 = ffma2(whz[2 * k],     hv1.x, z1);
            n1 = ffma2(whn[2 * k],     hv1.x, n1);
            r0 = ffma2(whr[2 * k + 1], hv0.y, r0);
            z0 = ffma2(whz[2 * k + 1], hv0.y, z0);
            n0 = ffma2(whn[2 * k + 1], hv0.y, n0);
            r1 = ffma2(whr[2 * k + 1], hv1.y, r1);
            z1 = ffma2(whz[2 * k + 1], hv1.y, z1);
            n1 = ffma2(whn[2 * k + 1], hv1.y, n1);
        }
        const float ar0 = xr0 + hsum2(r0);
        const float az0 = xz0 + hsum2(z0);
        const float hn0 = bhn + hsum2(n0);
        const float ar1 = xr1 + hsum2(r1);
        const float az1 = xz1 + hsum2(z1);
        const float hn1 = bhn + hsum2(n1);

        const float rr0 = sig_ap(ar0);
        const float zz0 = sig_ap(az0);
        const float nn0 = tanh_ap(fmaf(rr0, hn0, xn0));
        h0 = fmaf(zz0, h0 - nn0, nn0);
        const float rr1 = sig_ap(ar1);
        const float zz1 = sig_ap(az1);
        const float nn1 = tanh_ap(fmaf(rr1, hn1, xn1));
        h1 = fmaf(zz1, h1 - nn1, nn1);
    }

    // FC2 + FC epilogue for both rows
    {
        hbuf[wl][0][0][lane] = h0;
        hbuf[wl][0][1][lane] = h1;
        __syncwarp();
        const ulonglong2* hp0 =
            reinterpret_cast<const ulonglong2*>(&hbuf[wl][0][0][0]);
        const ulonglong2* hp1 =
            reinterpret_cast<const ulonglong2*>(&hbuf[wl][0][1][0]);
        const ull* wf = reinterpret_cast<const ull*>(Wfc2 + lane * HID);
        ull a0 = 0ull, a1 = 0ull;
#pragma unroll
        for (int k = 0; k < 8; k++) {
            const ulonglong2 hv0 = hp0[k];
            const ulonglong2 hv1 = hp1[k];
            a0 = ffma2(wf[2 * k],     hv0.x, a0);
            a1 = ffma2(wf[2 * k],     hv1.x, a1);
            a0 = ffma2(wf[2 * k + 1], hv0.y, a0);
            a1 = ffma2(wf[2 * k + 1], hv1.y, a1);
        }
        const float bf2 = __ldg(bfc2 + lane);
        const float o0 = bf2 + hsum2(a0);
        const float o1 = bf2 + hsum2(a1);

        const float wfc = __ldg(Wfc + lane);
        float p0 = wfc * o0;
        float p1 = wfc * o1;
#pragma unroll
        for (int off = 16; off > 0; off >>= 1) {
            p0 += __shfl_xor_sync(0xffffffffu, p0, off);
            p1 += __shfl_xor_sync(0xffffffffu, p1, off);
        }
        if (lane == 0) {
            const float bb = __ldg(bfc);
            out[warp * 2]     = p0 + bb;
            out[warp * 2 + 1] = p1 + bb;
        }
    }
}

// ---------------------------------------------------------------------------
// Launch
// ---------------------------------------------------------------------------
extern "C" void kernel_launch(void* const* d_in, const int* in_sizes, int n_in,
                              void* d_out, int out_size)
{
    const float* x     = (const float*)d_in[0];
    const float* Wih0  = (const float*)d_in[1];
    const float* Whh0  = (const float*)d_in[2];
    const float* bih0  = (const float*)d_in[3];
    const float* bhh0  = (const float*)d_in[4];
    const float* Wih1  = (const float*)d_in[5];
    const float* Whh1  = (const float*)d_in[6];
    const float* bih1  = (const float*)d_in[7];
    const float* bhh1  = (const float*)d_in[8];
    const float* Wfc2  = (const float*)d_in[9];
    const float* bfc2  = (const float*)d_in[10];
    const float* Wfc   = (const float*)d_in[11];
    const float* bfc   = (const float*)d_in[12];
    float* out = (float*)d_out;

    const int threads = 128;                 // 4 warps = 8 rows per CTA
    const int blocks  = NWARP / 4;           // 512 CTAs

    gru_layer1_fused_kernel<<<blocks, threads>>>(x, Wih0, Whh0, bih0, bhh0,
                                                 Wih1, bih1, bhh1);
    gru_layer2_fc_kernel<<<blocks, threads>>>(Whh1, bhh1,
                                              Wfc2, bfc2, Wfc, bfc, out);
}